// round 15
// baseline (speedup 1.0000x reference)
#include <cuda_runtime.h>
#include <cstdint>

#define Bn 8
#define Nn 8192
#define Sn 1024
#define Kn 32
#define C1c 64
#define C3c 128
#define Pn (Bn*Sn*Kn)   /* 262144 positions */
#define R2 0.04f

// ---------------- device scratch ------------------------------------------
static __device__ int   g_idx[Pn];
static __device__ float g_y1[(size_t)Pn*C1c];
static __device__ float g_y2[(size_t)Pn*C1c];
static __device__ float g_ymax[Bn*Sn*C3c];
static __device__ float g_ymin[Bn*Sn*C3c];
static __device__ float g_sum1[C1c], g_sq1[C1c], g_sum2[C1c], g_sq2[C1c];
static __device__ float g_sum3[C3c], g_sq3[C3c];

// ---------------- packed f32x2 helpers ------------------------------------
typedef unsigned long long u64p;
__device__ __forceinline__ u64p f2pack(float lo, float hi){ u64p r; asm("mov.b64 %0,{%1,%2};":"=l"(r):"f"(lo),"f"(hi)); return r; }
__device__ __forceinline__ void f2unpack(u64p v, float& lo, float& hi){ asm("mov.b64 {%0,%1},%2;":"=f"(lo),"=f"(hi):"l"(v)); }
__device__ __forceinline__ u64p f2add(u64p a, u64p b){ u64p r; asm("add.rn.f32x2 %0,%1,%2;":"=l"(r):"l"(a),"l"(b)); return r; }
__device__ __forceinline__ u64p f2mul(u64p a, u64p b){ u64p r; asm("mul.rn.f32x2 %0,%1,%2;":"=l"(r):"l"(a),"l"(b)); return r; }
__device__ __forceinline__ u64p f2fma(u64p a, u64p b, u64p c){ u64p r; asm("fma.rn.f32x2 %0,%1,%2,%3;":"=l"(r):"l"(a),"l"(b),"l"(c)); return r; }

// ============================ FPS (R9 + post-loop tmax tree) ==============
// The ONLY change vs the 744us R9 kernel: tmax is computed after the
// min-update loop via a balanced fmaxf tree (max is exact => bit-identical
// value; removes ~17 FMNMX/thread/step and the tmax serial dependence).
#define FPT 16
#define FTH 512
__global__ __launch_bounds__(FTH,1) void k_fps(const float* __restrict__ x,
                                               float* __restrict__ newx){
    __shared__ unsigned sWarpMax[FTH/32];
    __shared__ int sBest[2];
    const int b = blockIdx.x, tid = threadIdx.x, lane = tid & 31, wid = tid >> 5;
    if (b==0){  // fold stat zeroing into the first kernel
        if (tid<C1c){ g_sum1[tid]=0.f; g_sq1[tid]=0.f; g_sum2[tid]=0.f; g_sq2[tid]=0.f; }
        if (tid<C3c){ g_sum3[tid]=0.f; g_sq3[tid]=0.f; }
    }
    const float* xb = x + (size_t)b*Nn*3;
    float* nx = newx + (size_t)b*Sn*3;
    const int n0 = tid*FPT;

    u64p xq[FPT/2], yq[FPT/2], zq[FPT/2];
    float dist[FPT];
    #pragma unroll
    for (int i=0;i<FPT/2;i++){
        const float* p = xb + (size_t)(n0+2*i)*3;
        xq[i]=f2pack(p[0],p[3]); yq[i]=f2pack(p[1],p[4]); zq[i]=f2pack(p[2],p[5]);
    }
    #pragma unroll
    for (int i=0;i<FPT;i++) dist[i]=1e10f;
    if (tid==0) sBest[0]=0x7fffffff;
    __syncthreads();

    int farthest = 0;
    for (int s=0;s<Sn;s++){
        const float* cp = xb + (size_t)farthest*3;
        const float cx=cp[0], cy=cp[1], cz=cp[2];
        if (tid==0){ float* o = nx + s*3; o[0]=cx; o[1]=cy; o[2]=cz; }
        const u64p ncx=f2pack(-cx,-cx), ncy=f2pack(-cy,-cy), ncz=f2pack(-cz,-cz);
        #pragma unroll
        for (int i=0;i<FPT/2;i++){
            u64p dx=f2add(xq[i],ncx), dy=f2add(yq[i],ncy), dz=f2add(zq[i],ncz);
            u64p d2=f2add(f2add(f2mul(dx,dx),f2mul(dy,dy)),f2mul(dz,dz));
            float a,bb; f2unpack(d2,a,bb);
            dist[2*i]   = fminf(dist[2*i],a);
            dist[2*i+1] = fminf(dist[2*i+1],bb);
        }
        // balanced max tree (exact op => same tmax value as sequential)
        float t8[8];
        #pragma unroll
        for (int i=0;i<8;i++) t8[i]=fmaxf(dist[2*i],dist[2*i+1]);
        #pragma unroll
        for (int st=1;st<8;st<<=1)
            #pragma unroll
            for (int i=0;i<8;i+=2*st) t8[i]=fmaxf(t8[i],t8[i+st]);
        const float tmax = t8[0];
        const unsigned tb  = __float_as_uint(tmax);
        const unsigned wmb = __reduce_max_sync(0xffffffffu, tb);
        if (lane==0) sWarpMax[wid]=wmb;
        __syncthreads();                                   // bar1
        const int buf = s & 1;
        if (tid==0) sBest[1-buf]=0x7fffffff;
        const unsigned bmb = __reduce_max_sync(0xffffffffu, sWarpMax[lane & 15]);
        if (wmb==bmb && tb==wmb){
            const float v = __uint_as_float(bmb);
            int cand = 0x7fffffff;
            #pragma unroll
            for (int j=FPT-1;j>=0;j--){ if (dist[j]==v) cand = n0+j; }
            atomicMin(&sBest[buf], cand);
        }
        __syncthreads();                                   // bar2
        farthest = sBest[buf];
    }
}

// ============================ Ball query (R9 verbatim) ====================
__global__ __launch_bounds__(256) void k_ball(const float* __restrict__ x,
                                              const float* __restrict__ newx){
    const int w = blockIdx.x*(256/32) + (threadIdx.x>>5);
    const int lane = threadIdx.x & 31;
    const int b = w >> 10;
    const float* c = newx + (size_t)w*3;
    const float cx=c[0], cy=c[1], cz=c[2];
    const float cn = __fadd_rn(__fadd_rn(__fmul_rn(cx,cx),__fmul_rn(cy,cy)),__fmul_rn(cz,cz));
    const float* xb = x + (size_t)b*Nn*3;
    int total=0, first=0;
    for (int base=0; base<Nn && total<Kn; base+=32){
        const int n = base + lane;
        const float* p = xb + (size_t)n*3;
        const float px=p[0], py=p[1], pz=p[2];
        const float dot = __fadd_rn(__fadd_rn(__fmul_rn(cx,px),__fmul_rn(cy,py)),__fmul_rn(cz,pz));
        const float pn  = __fadd_rn(__fadd_rn(__fmul_rn(px,px),__fmul_rn(py,py)),__fmul_rn(pz,pz));
        const float sq  = __fadd_rn(__fadd_rn(__fmul_rn(-2.0f,dot),cn),pn);
        const bool pred = !(sq > R2);
        const unsigned mask = __ballot_sync(0xffffffffu, pred);
        if (total==0 && mask) first = base + __ffs(mask) - 1;
        const int slot = total + __popc(mask & ((1u<<lane)-1u));
        if (pred && slot < Kn) g_idx[w*Kn + slot] = n;
        total += __popc(mask);
    }
    if (total < Kn && lane >= total) g_idx[w*Kn + lane] = first;
}

// ---------------- BN finalize helper --------------------------------------
__device__ __forceinline__ void bn_fin(int t, const float* __restrict__ g,
                                       const float* __restrict__ be,
                                       const float* __restrict__ sums,
                                       const float* __restrict__ sqs,
                                       float* sc, float* sh){
    const float inv = 1.0f/(float)Pn;
    const float m = sums[t]*inv;
    const float v = fmaxf(sqs[t]*inv - m*m, 0.f);
    const float s = g[t]*rsqrtf(v + 1e-5f);
    sc[t] = s; sh[t] = fmaf(-m, s, be[t]);
}

// ============================ Layer 1 (3->64) + stats =====================
__global__ __launch_bounds__(256) void k_l1(const float* __restrict__ x,
                                            const float* __restrict__ newx,
                                            const float* __restrict__ W1,
                                            const float* __restrict__ b1){
    __shared__ float sh[128][3];
    __shared__ float redS[4][64], redQ[4][64];
    const int tid = threadIdx.x;
    const int p0  = blockIdx.x*128;
    if (tid < 128){
        const int p = p0 + tid;
        const int iv = g_idx[p];
        const int b = p >> 15;
        const int s = (p >> 5) & 1023;
        const float* pt = x    + ((size_t)b*Nn + iv)*3;
        const float* cc = newx + ((size_t)b*Sn + s)*3;
        sh[tid][0]=pt[0]-cc[0]; sh[tid][1]=pt[1]-cc[1]; sh[tid][2]=pt[2]-cc[2];
    }
    __syncthreads();
    const int c = tid & 63, pg = tid >> 6;
    const float w0=W1[c*3], w1=W1[c*3+1], w2=W1[c*3+2], bb=b1[c];
    float sm=0.f, sq=0.f;
    #pragma unroll 8
    for (int j=0;j<32;j++){
        const int pl = pg*32 + j;
        const float y = fmaf(sh[pl][0],w0, fmaf(sh[pl][1],w1, fmaf(sh[pl][2],w2, bb)));
        g_y1[(size_t)(p0+pl)*64 + c] = y;
        sm += y; sq = fmaf(y,y,sq);
    }
    redS[pg][c]=sm; redQ[pg][c]=sq;
    __syncthreads();
    if (tid < 64){
        atomicAdd(&g_sum1[tid], redS[0][tid]+redS[1][tid]+redS[2][tid]+redS[3][tid]);
        atomicAdd(&g_sq1[tid],  redQ[0][tid]+redQ[1][tid]+redQ[2][tid]+redQ[3][tid]);
    }
}

// ============================ Layer 2 (64->64) — R9 verbatim ==============
__global__ __launch_bounds__(256) void k_l2(const float* __restrict__ W2,
                                            const float* __restrict__ b2,
                                            const float* __restrict__ g1,
                                            const float* __restrict__ be1){
    __shared__ float sW[64][65];
    __shared__ float sh[64][64];
    __shared__ float ssc[64], sshb[64];
    __shared__ float redS[8][64], redQ[8][64];
    const int tid=threadIdx.x;
    const int p0 = blockIdx.x*64;
    if (tid<64) bn_fin(tid, g1, be1, g_sum1, g_sq1, ssc, sshb);
    #pragma unroll
    for (int j=0;j<16;j++){ const int l=tid+j*256; sW[l&63][l>>6]=W2[l]; }
    __syncthreads();
    #pragma unroll
    for (int j=0;j<4;j++){
        const int l4 = tid + j*256;
        float4 v = ((const float4*)g_y1)[(size_t)p0*16 + l4];
        const int ci0 = (l4&15)*4, pos = l4>>4;
        v.x = fmaxf(fmaf(ssc[ci0  ], v.x, sshb[ci0  ]), 0.f);
        v.y = fmaxf(fmaf(ssc[ci0+1], v.y, sshb[ci0+1]), 0.f);
        v.z = fmaxf(fmaf(ssc[ci0+2], v.z, sshb[ci0+2]), 0.f);
        v.w = fmaxf(fmaf(ssc[ci0+3], v.w, sshb[ci0+3]), 0.f);
        *(float4*)&sh[pos][ci0] = v;
    }
    __syncthreads();
    const int c0 = tid & 31, c1 = c0 + 32, pg = tid >> 5;
    u64p acc0[8], acc1[8];
    {
        const u64p i0 = f2pack(b2[c0], 0.f), i1 = f2pack(b2[c1], 0.f);
        #pragma unroll
        for (int i=0;i<8;i++){ acc0[i]=i0; acc1[i]=i1; }
    }
    #pragma unroll
    for (int ci0=0; ci0<64; ci0+=4){
        const u64p wA0 = f2pack(sW[ci0][c0],   sW[ci0+1][c0]);
        const u64p wB0 = f2pack(sW[ci0+2][c0], sW[ci0+3][c0]);
        const u64p wA1 = f2pack(sW[ci0][c1],   sW[ci0+1][c1]);
        const u64p wB1 = f2pack(sW[ci0+2][c1], sW[ci0+3][c1]);
        #pragma unroll
        for (int i=0;i<8;i++){
            const float4 h4 = *(const float4*)&sh[pg*8+i][ci0];
            const u64p hA = f2pack(h4.x,h4.y), hB = f2pack(h4.z,h4.w);
            acc0[i] = f2fma(hA, wA0, acc0[i]);
            acc0[i] = f2fma(hB, wB0, acc0[i]);
            acc1[i] = f2fma(hA, wA1, acc1[i]);
            acc1[i] = f2fma(hB, wB1, acc1[i]);
        }
    }
    float sm0=0.f,sq0=0.f,sm1=0.f,sq1=0.f;
    #pragma unroll
    for (int i=0;i<8;i++){
        float lo,hi; f2unpack(acc0[i],lo,hi);
        const float y0 = lo+hi;
        f2unpack(acc1[i],lo,hi);
        const float y1 = lo+hi;
        const size_t pr = (size_t)(p0+pg*8+i)*64;
        g_y2[pr+c0]=y0; g_y2[pr+c1]=y1;
        sm0+=y0; sq0=fmaf(y0,y0,sq0); sm1+=y1; sq1=fmaf(y1,y1,sq1);
    }
    redS[pg][c0]=sm0; redQ[pg][c0]=sq0; redS[pg][c1]=sm1; redQ[pg][c1]=sq1;
    __syncthreads();
    if (tid<64){
        float a=0.f,d=0.f;
        #pragma unroll
        for (int j=0;j<8;j++){ a+=redS[j][tid]; d+=redQ[j][tid]; }
        atomicAdd(&g_sum2[tid],a); atomicAdd(&g_sq2[tid],d);
    }
}

// ============================ Layer 3 (64->128) — R9 verbatim =============
__global__ __launch_bounds__(256) void k_l3(const float* __restrict__ W3,
                                            const float* __restrict__ b3,
                                            const float* __restrict__ g2,
                                            const float* __restrict__ be2){
    __shared__ float sW[64][129];
    __shared__ float sh[32][64];
    __shared__ float ssc[64], sshb[64];
    __shared__ float redS[4][128], redQ[4][128], redM[4][128], redN[4][128];
    const int tid=threadIdx.x;
    const int p0 = blockIdx.x*32;
    if (tid<64) bn_fin(tid, g2, be2, g_sum2, g_sq2, ssc, sshb);
    #pragma unroll
    for (int j=0;j<32;j++){ const int l=tid+j*256; sW[l&63][l>>6]=W3[l]; }
    __syncthreads();
    #pragma unroll
    for (int j=0;j<2;j++){
        const int l4 = tid + j*256;
        float4 v = ((const float4*)g_y2)[(size_t)p0*16 + l4];
        const int ci0 = (l4&15)*4, pos = l4>>4;
        v.x = fmaxf(fmaf(ssc[ci0  ], v.x, sshb[ci0  ]), 0.f);
        v.y = fmaxf(fmaf(ssc[ci0+1], v.y, sshb[ci0+1]), 0.f);
        v.z = fmaxf(fmaf(ssc[ci0+2], v.z, sshb[ci0+2]), 0.f);
        v.w = fmaxf(fmaf(ssc[ci0+3], v.w, sshb[ci0+3]), 0.f);
        *(float4*)&sh[pos][ci0] = v;
    }
    __syncthreads();
    const int c0 = tid & 63, c1 = c0 + 64, pg = tid >> 6;
    u64p acc0[8], acc1[8];
    {
        const u64p i0 = f2pack(b3[c0], 0.f), i1 = f2pack(b3[c1], 0.f);
        #pragma unroll
        for (int i=0;i<8;i++){ acc0[i]=i0; acc1[i]=i1; }
    }
    #pragma unroll
    for (int ci0=0; ci0<64; ci0+=4){
        const u64p wA0 = f2pack(sW[ci0][c0],   sW[ci0+1][c0]);
        const u64p wB0 = f2pack(sW[ci0+2][c0], sW[ci0+3][c0]);
        const u64p wA1 = f2pack(sW[ci0][c1],   sW[ci0+1][c1]);
        const u64p wB1 = f2pack(sW[ci0+2][c1], sW[ci0+3][c1]);
        #pragma unroll
        for (int i=0;i<8;i++){
            const float4 h4 = *(const float4*)&sh[pg*8+i][ci0];
            const u64p hA = f2pack(h4.x,h4.y), hB = f2pack(h4.z,h4.w);
            acc0[i] = f2fma(hA, wA0, acc0[i]);
            acc0[i] = f2fma(hB, wB0, acc0[i]);
            acc1[i] = f2fma(hA, wA1, acc1[i]);
            acc1[i] = f2fma(hB, wB1, acc1[i]);
        }
    }
    float sm0=0.f,sq0=0.f,mx0=-3.4e38f,mn0=3.4e38f;
    float sm1=0.f,sq1=0.f,mx1=-3.4e38f,mn1=3.4e38f;
    #pragma unroll
    for (int i=0;i<8;i++){
        float lo,hi; f2unpack(acc0[i],lo,hi);
        const float y0 = lo+hi;
        f2unpack(acc1[i],lo,hi);
        const float y1 = lo+hi;
        sm0+=y0; sq0=fmaf(y0,y0,sq0); mx0=fmaxf(mx0,y0); mn0=fminf(mn0,y0);
        sm1+=y1; sq1=fmaf(y1,y1,sq1); mx1=fmaxf(mx1,y1); mn1=fminf(mn1,y1);
    }
    redS[pg][c0]=sm0; redQ[pg][c0]=sq0; redM[pg][c0]=mx0; redN[pg][c0]=mn0;
    redS[pg][c1]=sm1; redQ[pg][c1]=sq1; redM[pg][c1]=mx1; redN[pg][c1]=mn1;
    __syncthreads();
    if (tid<128){
        float a=0.f,d=0.f,m=-3.4e38f,n=3.4e38f;
        #pragma unroll
        for (int j=0;j<4;j++){
            a+=redS[j][tid]; d+=redQ[j][tid];
            m=fmaxf(m,redM[j][tid]); n=fminf(n,redN[j][tid]);
        }
        g_ymax[(size_t)blockIdx.x*128 + tid] = m;
        g_ymin[(size_t)blockIdx.x*128 + tid] = n;
        atomicAdd(&g_sum3[tid],a); atomicAdd(&g_sq3[tid],d);
    }
}

// ============================ Output ======================================
__global__ __launch_bounds__(256) void k_out(const float* __restrict__ g3,
                                             const float* __restrict__ be3,
                                             float* __restrict__ feat){
    __shared__ float ssc[128], sshb[128];
    const int tid=threadIdx.x;
    if (tid<128) bn_fin(tid, g3, be3, g_sum3, g_sq3, ssc, sshb);
    __syncthreads();
    const int i = blockIdx.x*256 + tid;
    const int c = i & 127;
    const float sc = ssc[c], sb = sshb[c];
    const float v = (sc >= 0.f) ? g_ymax[i] : g_ymin[i];
    feat[i] = fmaxf(fmaf(sc, v, sb), 0.f);
}

// ============================ launch ======================================
extern "C" void kernel_launch(void* const* d_in, const int* in_sizes, int n_in,
                              void* d_out, int out_size){
    const float* x  = (const float*)d_in[0];
    const float* W1 = (const float*)d_in[1];  const float* b1 = (const float*)d_in[2];
    const float* g1 = (const float*)d_in[3];  const float* be1= (const float*)d_in[4];
    const float* W2 = (const float*)d_in[5];  const float* b2 = (const float*)d_in[6];
    const float* g2 = (const float*)d_in[7];  const float* be2= (const float*)d_in[8];
    const float* W3 = (const float*)d_in[9];  const float* b3 = (const float*)d_in[10];
    const float* g3 = (const float*)d_in[11]; const float* be3= (const float*)d_in[12];
    float* out  = (float*)d_out;
    float* newx = out;                 // (8,1024,3)
    float* feat = out + Bn*Sn*3;       // (8,1024,128)

    k_fps <<<Bn,FTH>>>(x, newx);
    k_ball<<<Sn*Bn/8,256>>>(x, newx);
    k_l1  <<<Pn/128,256>>>(x, newx, W1, b1);
    k_l2  <<<Pn/64,256>>>(W2, b2, g1, be1);
    k_l3  <<<Pn/32,256>>>(W3, b3, g2, be2);
    k_out <<<Pn*C3c/Kn/256,256>>>(g3, be3, feat);
}

// round 17
// speedup vs baseline: 1.0285x; 1.0285x over previous
#include <cuda_runtime.h>
#include <cstdint>

#define Bn 8
#define Nn 8192
#define Sn 1024
#define Kn 32
#define C1c 64
#define C3c 128
#define Pn (Bn*Sn*Kn)   /* 262144 positions */
#define R2 0.04f

// ---------------- device scratch ------------------------------------------
static __device__ int   g_idx[Pn];
static __device__ float g_y1[(size_t)Pn*C1c];
static __device__ float g_y2[(size_t)Pn*C1c];
static __device__ float g_ymax[Bn*Sn*C3c];
static __device__ float g_ymin[Bn*Sn*C3c];
static __device__ float g_sum1[C1c], g_sq1[C1c], g_sum2[C1c], g_sq2[C1c];
static __device__ float g_sum3[C3c], g_sq3[C3c];

// ---------------- packed f32x2 helpers ------------------------------------
typedef unsigned long long u64p;
__device__ __forceinline__ u64p f2pack(float lo, float hi){ u64p r; asm("mov.b64 %0,{%1,%2};":"=l"(r):"f"(lo),"f"(hi)); return r; }
__device__ __forceinline__ void f2unpack(u64p v, float& lo, float& hi){ asm("mov.b64 {%0,%1},%2;":"=f"(lo),"=f"(hi):"l"(v)); }
__device__ __forceinline__ u64p f2add(u64p a, u64p b){ u64p r; asm("add.rn.f32x2 %0,%1,%2;":"=l"(r):"l"(a),"l"(b)); return r; }
__device__ __forceinline__ u64p f2mul(u64p a, u64p b){ u64p r; asm("mul.rn.f32x2 %0,%1,%2;":"=l"(r):"l"(a),"l"(b)); return r; }
__device__ __forceinline__ u64p f2fma(u64p a, u64p b, u64p c){ u64p r; asm("fma.rn.f32x2 %0,%1,%2,%3;":"=l"(r):"l"(a),"l"(b),"l"(c)); return r; }

// ============================ FPS (R9 verbatim — 744us proven) ============
// Distance math: mul/add.rn f32x2 + sequential fminf/fmaxf (no contraction).
// Reduction: REDUX warp max; LDS+REDUX block max; winner-warp rescan +
// atomicMin into double-buffered sBest; two barriers per step.
#define FPT 16
#define FTH 512
__global__ __launch_bounds__(FTH,1) void k_fps(const float* __restrict__ x,
                                               float* __restrict__ newx){
    __shared__ unsigned sWarpMax[FTH/32];
    __shared__ int sBest[2];
    const int b = blockIdx.x, tid = threadIdx.x, lane = tid & 31, wid = tid >> 5;
    if (b==0){  // fold stat zeroing into the first kernel
        if (tid<C1c){ g_sum1[tid]=0.f; g_sq1[tid]=0.f; g_sum2[tid]=0.f; g_sq2[tid]=0.f; }
        if (tid<C3c){ g_sum3[tid]=0.f; g_sq3[tid]=0.f; }
    }
    const float* xb = x + (size_t)b*Nn*3;
    float* nx = newx + (size_t)b*Sn*3;
    const int n0 = tid*FPT;

    u64p xq[FPT/2], yq[FPT/2], zq[FPT/2];
    float dist[FPT];
    #pragma unroll
    for (int i=0;i<FPT/2;i++){
        const float* p = xb + (size_t)(n0+2*i)*3;
        xq[i]=f2pack(p[0],p[3]); yq[i]=f2pack(p[1],p[4]); zq[i]=f2pack(p[2],p[5]);
    }
    #pragma unroll
    for (int i=0;i<FPT;i++) dist[i]=1e10f;
    if (tid==0) sBest[0]=0x7fffffff;
    __syncthreads();

    int farthest = 0;
    for (int s=0;s<Sn;s++){
        const float* cp = xb + (size_t)farthest*3;
        const float cx=cp[0], cy=cp[1], cz=cp[2];
        if (tid==0){ float* o = nx + s*3; o[0]=cx; o[1]=cy; o[2]=cz; }
        const u64p ncx=f2pack(-cx,-cx), ncy=f2pack(-cy,-cy), ncz=f2pack(-cz,-cz);
        float tmax = -3.4e38f;
        #pragma unroll
        for (int i=0;i<FPT/2;i++){
            u64p dx=f2add(xq[i],ncx), dy=f2add(yq[i],ncy), dz=f2add(zq[i],ncz);
            u64p d2=f2add(f2add(f2mul(dx,dx),f2mul(dy,dy)),f2mul(dz,dz));
            float a,bb; f2unpack(d2,a,bb);
            dist[2*i]   = fminf(dist[2*i],a);
            dist[2*i+1] = fminf(dist[2*i+1],bb);
            tmax = fmaxf(tmax, fmaxf(dist[2*i], dist[2*i+1]));
        }
        const unsigned tb  = __float_as_uint(tmax);
        const unsigned wmb = __reduce_max_sync(0xffffffffu, tb);
        if (lane==0) sWarpMax[wid]=wmb;
        __syncthreads();                                   // bar1
        const int buf = s & 1;
        if (tid==0) sBest[1-buf]=0x7fffffff;
        const unsigned bmb = __reduce_max_sync(0xffffffffu, sWarpMax[lane & 15]);
        if (wmb==bmb && tb==wmb){
            const float v = __uint_as_float(bmb);
            int cand = 0x7fffffff;
            #pragma unroll
            for (int j=FPT-1;j>=0;j--){ if (dist[j]==v) cand = n0+j; }
            atomicMin(&sBest[buf], cand);
        }
        __syncthreads();                                   // bar2
        farthest = sBest[buf];
    }
}

// ============================ Ball query (R9 verbatim) ====================
__global__ __launch_bounds__(256) void k_ball(const float* __restrict__ x,
                                              const float* __restrict__ newx){
    const int w = blockIdx.x*(256/32) + (threadIdx.x>>5);
    const int lane = threadIdx.x & 31;
    const int b = w >> 10;
    const float* c = newx + (size_t)w*3;
    const float cx=c[0], cy=c[1], cz=c[2];
    const float cn = __fadd_rn(__fadd_rn(__fmul_rn(cx,cx),__fmul_rn(cy,cy)),__fmul_rn(cz,cz));
    const float* xb = x + (size_t)b*Nn*3;
    int total=0, first=0;
    for (int base=0; base<Nn && total<Kn; base+=32){
        const int n = base + lane;
        const float* p = xb + (size_t)n*3;
        const float px=p[0], py=p[1], pz=p[2];
        const float dot = __fadd_rn(__fadd_rn(__fmul_rn(cx,px),__fmul_rn(cy,py)),__fmul_rn(cz,pz));
        const float pn  = __fadd_rn(__fadd_rn(__fmul_rn(px,px),__fmul_rn(py,py)),__fmul_rn(pz,pz));
        const float sq  = __fadd_rn(__fadd_rn(__fmul_rn(-2.0f,dot),cn),pn);
        const bool pred = !(sq > R2);
        const unsigned mask = __ballot_sync(0xffffffffu, pred);
        if (total==0 && mask) first = base + __ffs(mask) - 1;
        const int slot = total + __popc(mask & ((1u<<lane)-1u));
        if (pred && slot < Kn) g_idx[w*Kn + slot] = n;
        total += __popc(mask);
    }
    if (total < Kn && lane >= total) g_idx[w*Kn + lane] = first;
}

// ---------------- BN finalize helper --------------------------------------
__device__ __forceinline__ void bn_fin(int t, const float* __restrict__ g,
                                       const float* __restrict__ be,
                                       const float* __restrict__ sums,
                                       const float* __restrict__ sqs,
                                       float* sc, float* sh){
    const float inv = 1.0f/(float)Pn;
    const float m = sums[t]*inv;
    const float v = fmaxf(sqs[t]*inv - m*m, 0.f);
    const float s = g[t]*rsqrtf(v + 1e-5f);
    sc[t] = s; sh[t] = fmaf(-m, s, be[t]);
}

// ============================ Layer 1 (3->64) + stats =====================
__global__ __launch_bounds__(256) void k_l1(const float* __restrict__ x,
                                            const float* __restrict__ newx,
                                            const float* __restrict__ W1,
                                            const float* __restrict__ b1){
    __shared__ float sh[128][3];
    __shared__ float redS[4][64], redQ[4][64];
    const int tid = threadIdx.x;
    const int p0  = blockIdx.x*128;
    if (tid < 128){
        const int p = p0 + tid;
        const int iv = g_idx[p];
        const int b = p >> 15;
        const int s = (p >> 5) & 1023;
        const float* pt = x    + ((size_t)b*Nn + iv)*3;
        const float* cc = newx + ((size_t)b*Sn + s)*3;
        sh[tid][0]=pt[0]-cc[0]; sh[tid][1]=pt[1]-cc[1]; sh[tid][2]=pt[2]-cc[2];
    }
    __syncthreads();
    const int c = tid & 63, pg = tid >> 6;
    const float w0=W1[c*3], w1=W1[c*3+1], w2=W1[c*3+2], bb=b1[c];
    float sm=0.f, sq=0.f;
    #pragma unroll 8
    for (int j=0;j<32;j++){
        const int pl = pg*32 + j;
        const float y = fmaf(sh[pl][0],w0, fmaf(sh[pl][1],w1, fmaf(sh[pl][2],w2, bb)));
        g_y1[(size_t)(p0+pl)*64 + c] = y;
        sm += y; sq = fmaf(y,y,sq);
    }
    redS[pg][c]=sm; redQ[pg][c]=sq;
    __syncthreads();
    if (tid < 64){
        atomicAdd(&g_sum1[tid], redS[0][tid]+redS[1][tid]+redS[2][tid]+redS[3][tid]);
        atomicAdd(&g_sq1[tid],  redQ[0][tid]+redQ[1][tid]+redQ[2][tid]+redQ[3][tid]);
    }
}

// ============================ Layer 2 (64->64) — R9 verbatim ==============
__global__ __launch_bounds__(256) void k_l2(const float* __restrict__ W2,
                                            const float* __restrict__ b2,
                                            const float* __restrict__ g1,
                                            const float* __restrict__ be1){
    __shared__ float sW[64][65];
    __shared__ float sh[64][64];
    __shared__ float ssc[64], sshb[64];
    __shared__ float redS[8][64], redQ[8][64];
    const int tid=threadIdx.x;
    const int p0 = blockIdx.x*64;
    if (tid<64) bn_fin(tid, g1, be1, g_sum1, g_sq1, ssc, sshb);
    #pragma unroll
    for (int j=0;j<16;j++){ const int l=tid+j*256; sW[l&63][l>>6]=W2[l]; }
    __syncthreads();
    #pragma unroll
    for (int j=0;j<4;j++){
        const int l4 = tid + j*256;
        float4 v = ((const float4*)g_y1)[(size_t)p0*16 + l4];
        const int ci0 = (l4&15)*4, pos = l4>>4;
        v.x = fmaxf(fmaf(ssc[ci0  ], v.x, sshb[ci0  ]), 0.f);
        v.y = fmaxf(fmaf(ssc[ci0+1], v.y, sshb[ci0+1]), 0.f);
        v.z = fmaxf(fmaf(ssc[ci0+2], v.z, sshb[ci0+2]), 0.f);
        v.w = fmaxf(fmaf(ssc[ci0+3], v.w, sshb[ci0+3]), 0.f);
        *(float4*)&sh[pos][ci0] = v;
    }
    __syncthreads();
    const int c0 = tid & 31, c1 = c0 + 32, pg = tid >> 5;
    u64p acc0[8], acc1[8];
    {
        const u64p i0 = f2pack(b2[c0], 0.f), i1 = f2pack(b2[c1], 0.f);
        #pragma unroll
        for (int i=0;i<8;i++){ acc0[i]=i0; acc1[i]=i1; }
    }
    #pragma unroll
    for (int ci0=0; ci0<64; ci0+=4){
        const u64p wA0 = f2pack(sW[ci0][c0],   sW[ci0+1][c0]);
        const u64p wB0 = f2pack(sW[ci0+2][c0], sW[ci0+3][c0]);
        const u64p wA1 = f2pack(sW[ci0][c1],   sW[ci0+1][c1]);
        const u64p wB1 = f2pack(sW[ci0+2][c1], sW[ci0+3][c1]);
        #pragma unroll
        for (int i=0;i<8;i++){
            const float4 h4 = *(const float4*)&sh[pg*8+i][ci0];
            const u64p hA = f2pack(h4.x,h4.y), hB = f2pack(h4.z,h4.w);
            acc0[i] = f2fma(hA, wA0, acc0[i]);
            acc0[i] = f2fma(hB, wB0, acc0[i]);
            acc1[i] = f2fma(hA, wA1, acc1[i]);
            acc1[i] = f2fma(hB, wB1, acc1[i]);
        }
    }
    float sm0=0.f,sq0=0.f,sm1=0.f,sq1=0.f;
    #pragma unroll
    for (int i=0;i<8;i++){
        float lo,hi; f2unpack(acc0[i],lo,hi);
        const float y0 = lo+hi;
        f2unpack(acc1[i],lo,hi);
        const float y1 = lo+hi;
        const size_t pr = (size_t)(p0+pg*8+i)*64;
        g_y2[pr+c0]=y0; g_y2[pr+c1]=y1;
        sm0+=y0; sq0=fmaf(y0,y0,sq0); sm1+=y1; sq1=fmaf(y1,y1,sq1);
    }
    redS[pg][c0]=sm0; redQ[pg][c0]=sq0; redS[pg][c1]=sm1; redQ[pg][c1]=sq1;
    __syncthreads();
    if (tid<64){
        float a=0.f,d=0.f;
        #pragma unroll
        for (int j=0;j<8;j++){ a+=redS[j][tid]; d+=redQ[j][tid]; }
        atomicAdd(&g_sum2[tid],a); atomicAdd(&g_sq2[tid],d);
    }
}

// ============================ Layer 3 (64->128) — R9 verbatim =============
__global__ __launch_bounds__(256) void k_l3(const float* __restrict__ W3,
                                            const float* __restrict__ b3,
                                            const float* __restrict__ g2,
                                            const float* __restrict__ be2){
    __shared__ float sW[64][129];
    __shared__ float sh[32][64];
    __shared__ float ssc[64], sshb[64];
    __shared__ float redS[4][128], redQ[4][128], redM[4][128], redN[4][128];
    const int tid=threadIdx.x;
    const int p0 = blockIdx.x*32;
    if (tid<64) bn_fin(tid, g2, be2, g_sum2, g_sq2, ssc, sshb);
    #pragma unroll
    for (int j=0;j<32;j++){ const int l=tid+j*256; sW[l&63][l>>6]=W3[l]; }
    __syncthreads();
    #pragma unroll
    for (int j=0;j<2;j++){
        const int l4 = tid + j*256;
        float4 v = ((const float4*)g_y2)[(size_t)p0*16 + l4];
        const int ci0 = (l4&15)*4, pos = l4>>4;
        v.x = fmaxf(fmaf(ssc[ci0  ], v.x, sshb[ci0  ]), 0.f);
        v.y = fmaxf(fmaf(ssc[ci0+1], v.y, sshb[ci0+1]), 0.f);
        v.z = fmaxf(fmaf(ssc[ci0+2], v.z, sshb[ci0+2]), 0.f);
        v.w = fmaxf(fmaf(ssc[ci0+3], v.w, sshb[ci0+3]), 0.f);
        *(float4*)&sh[pos][ci0] = v;
    }
    __syncthreads();
    const int c0 = tid & 63, c1 = c0 + 64, pg = tid >> 6;
    u64p acc0[8], acc1[8];
    {
        const u64p i0 = f2pack(b3[c0], 0.f), i1 = f2pack(b3[c1], 0.f);
        #pragma unroll
        for (int i=0;i<8;i++){ acc0[i]=i0; acc1[i]=i1; }
    }
    #pragma unroll
    for (int ci0=0; ci0<64; ci0+=4){
        const u64p wA0 = f2pack(sW[ci0][c0],   sW[ci0+1][c0]);
        const u64p wB0 = f2pack(sW[ci0+2][c0], sW[ci0+3][c0]);
        const u64p wA1 = f2pack(sW[ci0][c1],   sW[ci0+1][c1]);
        const u64p wB1 = f2pack(sW[ci0+2][c1], sW[ci0+3][c1]);
        #pragma unroll
        for (int i=0;i<8;i++){
            const float4 h4 = *(const float4*)&sh[pg*8+i][ci0];
            const u64p hA = f2pack(h4.x,h4.y), hB = f2pack(h4.z,h4.w);
            acc0[i] = f2fma(hA, wA0, acc0[i]);
            acc0[i] = f2fma(hB, wB0, acc0[i]);
            acc1[i] = f2fma(hA, wA1, acc1[i]);
            acc1[i] = f2fma(hB, wB1, acc1[i]);
        }
    }
    float sm0=0.f,sq0=0.f,mx0=-3.4e38f,mn0=3.4e38f;
    float sm1=0.f,sq1=0.f,mx1=-3.4e38f,mn1=3.4e38f;
    #pragma unroll
    for (int i=0;i<8;i++){
        float lo,hi; f2unpack(acc0[i],lo,hi);
        const float y0 = lo+hi;
        f2unpack(acc1[i],lo,hi);
        const float y1 = lo+hi;
        sm0+=y0; sq0=fmaf(y0,y0,sq0); mx0=fmaxf(mx0,y0); mn0=fminf(mn0,y0);
        sm1+=y1; sq1=fmaf(y1,y1,sq1); mx1=fmaxf(mx1,y1); mn1=fminf(mn1,y1);
    }
    redS[pg][c0]=sm0; redQ[pg][c0]=sq0; redM[pg][c0]=mx0; redN[pg][c0]=mn0;
    redS[pg][c1]=sm1; redQ[pg][c1]=sq1; redM[pg][c1]=mx1; redN[pg][c1]=mn1;
    __syncthreads();
    if (tid<128){
        float a=0.f,d=0.f,m=-3.4e38f,n=3.4e38f;
        #pragma unroll
        for (int j=0;j<4;j++){
            a+=redS[j][tid]; d+=redQ[j][tid];
            m=fmaxf(m,redM[j][tid]); n=fminf(n,redN[j][tid]);
        }
        g_ymax[(size_t)blockIdx.x*128 + tid] = m;
        g_ymin[(size_t)blockIdx.x*128 + tid] = n;
        atomicAdd(&g_sum3[tid],a); atomicAdd(&g_sq3[tid],d);
    }
}

// ============================ Output ======================================
__global__ __launch_bounds__(256) void k_out(const float* __restrict__ g3,
                                             const float* __restrict__ be3,
                                             float* __restrict__ feat){
    __shared__ float ssc[128], sshb[128];
    const int tid=threadIdx.x;
    if (tid<128) bn_fin(tid, g3, be3, g_sum3, g_sq3, ssc, sshb);
    __syncthreads();
    const int i = blockIdx.x*256 + tid;
    const int c = i & 127;
    const float sc = ssc[c], sb = sshb[c];
    const float v = (sc >= 0.f) ? g_ymax[i] : g_ymin[i];
    feat[i] = fmaxf(fmaf(sc, v, sb), 0.f);
}

// ============================ launch ======================================
extern "C" void kernel_launch(void* const* d_in, const int* in_sizes, int n_in,
                              void* d_out, int out_size){
    const float* x  = (const float*)d_in[0];
    const float* W1 = (const float*)d_in[1];  const float* b1 = (const float*)d_in[2];
    const float* g1 = (const float*)d_in[3];  const float* be1= (const float*)d_in[4];
    const float* W2 = (const float*)d_in[5];  const float* b2 = (const float*)d_in[6];
    const float* g2 = (const float*)d_in[7];  const float* be2= (const float*)d_in[8];
    const float* W3 = (const float*)d_in[9];  const float* b3 = (const float*)d_in[10];
    const float* g3 = (const float*)d_in[11]; const float* be3= (const float*)d_in[12];
    float* out  = (float*)d_out;
    float* newx = out;                 // (8,1024,3)
    float* feat = out + Bn*Sn*3;       // (8,1024,128)

    k_fps <<<Bn,FTH>>>(x, newx);
    k_ball<<<Sn*Bn/8,256>>>(x, newx);
    k_l1  <<<Pn/128,256>>>(x, newx, W1, b1);
    k_l2  <<<Pn/64,256>>>(W2, b2, g1, be1);
    k_l3  <<<Pn/32,256>>>(W3, b3, g2, be2);
    k_out <<<Pn*C3c/Kn/256,256>>>(g3, be3, feat);
}